// round 3
// baseline (speedup 1.0000x reference)
#include <cuda_runtime.h>
#include <math.h>

// Problem dimensions (fixed by the dataset)
#define NN    32768      // total nodes B*NPG
#define BBg   8          // graphs
#define NPGc  4096       // nodes per graph
#define DINc  128
#define HHc   4
#define EEc   262144
#define CDIM  512        // H*DIN
#define BHc   32         // B*H

// ---------------- scratch (device globals: allocation-free) ----------------
__device__ float g_q  [NN*CDIM];
__device__ float g_k  [NN*CDIM];
__device__ float g_cur[NN*CDIM];
__device__ float g_acc[NN*CDIM];
__device__ float g_gcn[NN*CDIM];
__device__ float g_kv  [BHc*DINc*DINc];
__device__ float g_vsum[BHc*DINc];
__device__ float g_ksum[BHc*DINc];
__device__ float g_den [NN*HHc];
__device__ int   g_deg   [NN];
__device__ float g_dis   [NN];
__device__ int   g_cursor[NN];
__device__ int   g_rowptr[NN];
__device__ int   g_incl  [NN];
__device__ int   g_bsum[128];
__device__ int   g_boff[128];
__device__ int   g_ecol[EEc];
__device__ float g_ew  [EEc];

// ---------------- init: cur = acc = broadcast(x over heads) ----------------
__global__ void k_init(const float* __restrict__ x) {
    int i = blockIdx.x * blockDim.x + threadIdx.x;     // float4 index over NN*CDIM/4
    int n  = i >> 7;            // 128 float4 per node
    int r  = i & 127;
    int d4 = r & 31;            // float4 within the 128-dim feature (head-replicated)
    float4 v = reinterpret_cast<const float4*>(x)[n * 32 + d4];
    reinterpret_cast<float4*>(g_cur)[i] = v;
    reinterpret_cast<float4*>(g_acc)[i] = v;
}

__global__ void k_zero_pre() {
    int i = blockIdx.x * blockDim.x + threadIdx.x;
    if (i < NN) { g_deg[i] = 0; g_cursor[i] = 0; }
    if (i < BHc * DINc) g_ksum[i] = 0.f;
}

__global__ void k_count(const int* __restrict__ row) {
    int e = blockIdx.x * blockDim.x + threadIdx.x;
    if (e < EEc) atomicAdd(&g_deg[row[e]], 1);
}

__global__ void k_dis() {
    int n = blockIdx.x * blockDim.x + threadIdx.x;
    if (n < NN) {
        int d = g_deg[n];
        g_dis[n] = (d > 0) ? (1.0f / sqrtf((float)d)) : 0.0f;
    }
}

// ---------------- prefix scan over deg -> rowptr (exclusive) ----------------
__global__ void k_scanA() {
    __shared__ int s[256];
    int t = threadIdx.x;
    int i = blockIdx.x * 256 + t;
    int v = g_deg[i];
    s[t] = v; __syncthreads();
    for (int off = 1; off < 256; off <<= 1) {
        int u = (t >= off) ? s[t - off] : 0;
        __syncthreads();
        s[t] += u;
        __syncthreads();
    }
    g_incl[i] = s[t];
    if (t == 255) g_bsum[blockIdx.x] = s[255];
}

__global__ void k_scanB() {
    __shared__ int s[128];
    int t = threadIdx.x;
    int v = g_bsum[t];
    s[t] = v; __syncthreads();
    for (int off = 1; off < 128; off <<= 1) {
        int u = (t >= off) ? s[t - off] : 0;
        __syncthreads();
        s[t] += u;
        __syncthreads();
    }
    g_boff[t] = s[t] - v;     // exclusive block offset
}

__global__ void k_scanC() {
    int i = blockIdx.x * blockDim.x + threadIdx.x;
    if (i < NN) g_rowptr[i] = g_incl[i] - g_deg[i] + g_boff[i >> 8];
}

__global__ void k_fill(const int* __restrict__ row, const int* __restrict__ col) {
    int e = blockIdx.x * blockDim.x + threadIdx.x;
    if (e < EEc) {
        int r = row[e], c = col[e];
        int pos = g_rowptr[r] + atomicAdd(&g_cursor[r], 1);
        g_ecol[pos] = c;
        g_ew[pos]   = g_dis[r] * g_dis[c];
    }
}

// ---------------- generic SGEMM: C[M,N] = scale*(A[M,K] @ B[N,K]^T + bias[N]) ----------------
// 128x128 tile, 256 threads, 8x8 per thread, K chunked by 32.
__global__ void k_gemm(const float* __restrict__ A, const float* __restrict__ B,
                       const float* __restrict__ bias, float* __restrict__ C,
                       int M, int N, int K, float scale) {
    __shared__ __align__(16) float sA[32 * 132];
    __shared__ __align__(16) float sB[32 * 132];
    int t  = threadIdx.x;
    int bm = blockIdx.y * 128;
    int bn = blockIdx.x * 128;
    int m0 = (t >> 4) * 8;
    int n0 = (t & 15) * 8;

    float acc[8][8];
    #pragma unroll
    for (int i = 0; i < 8; i++)
        #pragma unroll
        for (int j = 0; j < 8; j++) acc[i][j] = 0.f;

    for (int kc = 0; kc < K; kc += 32) {
        #pragma unroll
        for (int l = 0; l < 4; l++) {
            int id = t + 256 * l;          // 0..1023
            int m  = id >> 3;
            int c4 = (id & 7) * 4;
            float4 va = *reinterpret_cast<const float4*>(&A[(bm + m) * K + kc + c4]);
            sA[(c4 + 0) * 132 + m] = va.x;
            sA[(c4 + 1) * 132 + m] = va.y;
            sA[(c4 + 2) * 132 + m] = va.z;
            sA[(c4 + 3) * 132 + m] = va.w;
            float4 vb = *reinterpret_cast<const float4*>(&B[(bn + m) * K + kc + c4]);
            sB[(c4 + 0) * 132 + m] = vb.x;
            sB[(c4 + 1) * 132 + m] = vb.y;
            sB[(c4 + 2) * 132 + m] = vb.z;
            sB[(c4 + 3) * 132 + m] = vb.w;
        }
        __syncthreads();
        #pragma unroll
        for (int k = 0; k < 32; k++) {
            float a[8], b[8];
            *reinterpret_cast<float4*>(a)     = *reinterpret_cast<float4*>(&sA[k * 132 + m0]);
            *reinterpret_cast<float4*>(a + 4) = *reinterpret_cast<float4*>(&sA[k * 132 + m0 + 4]);
            *reinterpret_cast<float4*>(b)     = *reinterpret_cast<float4*>(&sB[k * 132 + n0]);
            *reinterpret_cast<float4*>(b + 4) = *reinterpret_cast<float4*>(&sB[k * 132 + n0 + 4]);
            #pragma unroll
            for (int i = 0; i < 8; i++)
                #pragma unroll
                for (int j = 0; j < 8; j++) acc[i][j] += a[i] * b[j];
        }
        __syncthreads();
    }

    float bb[8];
    #pragma unroll
    for (int j = 0; j < 8; j++) bb[j] = bias[bn + n0 + j];
    #pragma unroll
    for (int i = 0; i < 8; i++) {
        int gm = bm + m0 + i;
        #pragma unroll
        for (int j = 0; j < 8; j += 4) {
            float4 o;
            o.x = scale * (acc[i][j + 0] + bb[j + 0]);
            o.y = scale * (acc[i][j + 1] + bb[j + 1]);
            o.z = scale * (acc[i][j + 2] + bb[j + 2]);
            o.w = scale * (acc[i][j + 3] + bb[j + 3]);
            *reinterpret_cast<float4*>(&C[gm * N + bn + n0 + j]) = o;
        }
    }
}

// ---------------- L2-normalize rows of 128 (one warp per (n,h)) ----------------
__global__ void k_norm(float* __restrict__ buf) {
    int gt   = blockIdx.x * blockDim.x + threadIdx.x;
    int w    = gt >> 5;                 // warp over NN*HH rows
    int lane = threadIdx.x & 31;
    float4 v = reinterpret_cast<float4*>(buf)[w * 32 + lane];
    float ss = v.x * v.x + v.y * v.y + v.z * v.z + v.w * v.w;
    #pragma unroll
    for (int off = 16; off > 0; off >>= 1) ss += __shfl_xor_sync(0xffffffffu, ss, off);
    float r = 1.0f / sqrtf(ss);
    v.x *= r; v.y *= r; v.z *= r; v.w *= r;
    reinterpret_cast<float4*>(buf)[w * 32 + lane] = v;
}

// ---------------- column sums over nodes per (b,h): which==0 -> ksum from g_k, 1 -> vsum from g_cur
__global__ void k_colsum(int which) {
    int bh = blockIdx.x;
    int b = bh >> 2, h = bh & 3;
    int nb = blockIdx.y * 128;
    int e = threadIdx.x;
    const float* src = which ? g_cur : g_k;
    float* dst       = which ? g_vsum : g_ksum;
    float s = 0.f;
    for (int n = 0; n < 128; n++)
        s += src[((b * NPGc + nb + n) * HHc + h) * DINc + e];
    atomicAdd(&dst[bh * DINc + e], s);
}

// ---------------- den[n,h] = q . ksum + n_nodes (iteration-invariant) ----------------
__global__ void k_den(const int* __restrict__ n_nodes) {
    int gt   = blockIdx.x * blockDim.x + threadIdx.x;
    int w    = gt >> 5;                 // (n,h) index
    int lane = threadIdx.x & 31;
    int n = w >> 2, h = w & 3;
    int b = n >> 12;                    // NPG = 4096
    float4 q = reinterpret_cast<float4*>(g_q)[w * 32 + lane];
    float4 s = reinterpret_cast<float4*>(g_ksum)[((b << 2) | h) * 32 + lane];
    float d = q.x * s.x + q.y * s.y + q.z * s.z + q.w * s.w;
    #pragma unroll
    for (int off = 16; off > 0; off >>= 1) d += __shfl_xor_sync(0xffffffffu, d, off);
    if (lane == 0) g_den[w] = d + (float)n_nodes[b];
}

__global__ void k_zero_iter() {
    int i = blockIdx.x * blockDim.x + threadIdx.x;
    if (i < BHc * DINc * DINc) g_kv[i] = 0.f;
    if (i < BHc * DINc) g_vsum[i] = 0.f;
}

// ---------------- kv[b,h] = sum_n k[n] (outer) v[n]  (split over node chunks) ----------------
__global__ void k_kv() {
    __shared__ __align__(16) float sK[16 * 128];
    __shared__ __align__(16) float sV[16 * 128];
    int bh = blockIdx.x, sp = blockIdx.y;
    int b = bh >> 2, h = bh & 3;
    int t = threadIdx.x;
    int m0 = (t >> 4) * 8;
    int e0 = (t & 15) * 8;
    int nbase = sp * 512;

    float acc[8][8];
    #pragma unroll
    for (int i = 0; i < 8; i++)
        #pragma unroll
        for (int j = 0; j < 8; j++) acc[i][j] = 0.f;

    for (int st = 0; st < 512; st += 16) {
        #pragma unroll
        for (int l = 0; l < 4; l++) {
            int id = t + 256 * l;                  // 0..1023 float4 slots
            if (id < 512) {
                int nl = id >> 5, d4 = id & 31;
                int fidx = ((b * NPGc + nbase + st + nl) * HHc + h) * DINc + d4 * 4;
                reinterpret_cast<float4*>(sK)[nl * 32 + d4] =
                    *reinterpret_cast<const float4*>(&g_k[fidx]);
            } else {
                int id2 = id - 512;
                int nl = id2 >> 5, d4 = id2 & 31;
                int fidx = ((b * NPGc + nbase + st + nl) * HHc + h) * DINc + d4 * 4;
                reinterpret_cast<float4*>(sV)[nl * 32 + d4] =
                    *reinterpret_cast<const float4*>(&g_cur[fidx]);
            }
        }
        __syncthreads();
        #pragma unroll
        for (int n = 0; n < 16; n++) {
            float a[8], v[8];
            *reinterpret_cast<float4*>(a)     = *reinterpret_cast<float4*>(&sK[n * 128 + m0]);
            *reinterpret_cast<float4*>(a + 4) = *reinterpret_cast<float4*>(&sK[n * 128 + m0 + 4]);
            *reinterpret_cast<float4*>(v)     = *reinterpret_cast<float4*>(&sV[n * 128 + e0]);
            *reinterpret_cast<float4*>(v + 4) = *reinterpret_cast<float4*>(&sV[n * 128 + e0 + 4]);
            #pragma unroll
            for (int i = 0; i < 8; i++)
                #pragma unroll
                for (int j = 0; j < 8; j++) acc[i][j] += a[i] * v[j];
        }
        __syncthreads();
    }
    float* dst = &g_kv[bh * DINc * DINc];
    #pragma unroll
    for (int i = 0; i < 8; i++)
        #pragma unroll
        for (int j = 0; j < 8; j++)
            atomicAdd(&dst[(m0 + i) * 128 + e0 + j], acc[i][j]);
}

// ---------------- GCN gather: gcn[n] = sum_{e in CSR row n} w[e] * cur[col[e]] ----------------
__global__ void k_gcn() {
    int n = blockIdx.x;
    int t = threadIdx.x;             // 0..127, one float4 of the 512-wide feature
    int s = g_rowptr[n];
    int e = s + g_deg[n];
    float4 acc = make_float4(0.f, 0.f, 0.f, 0.f);
    for (int i = s; i < e; i++) {
        int   c = g_ecol[i];
        float w = g_ew[i];
        float4 v = reinterpret_cast<const float4*>(g_cur)[c * 128 + t];
        acc.x += w * v.x; acc.y += w * v.y; acc.z += w * v.z; acc.w += w * v.w;
    }
    reinterpret_cast<float4*>(g_gcn)[n * 128 + t] = acc;
}

// ---------------- combine: attn = (q@kv + vsum)/den; cur = .5*gcn + .5*attn; acc += cur ----------------
__global__ void k_combine() {
    extern __shared__ __align__(16) float sm[];
    float* sKV = sm;                 // 128*128
    float* sQ  = sm + 16384;         // 64*128
    int bh = blockIdx.x, ch = blockIdx.y;
    int b = bh >> 2, h = bh & 3;
    int t = threadIdx.x;             // 128 threads
    int nbase = ch * 64;

    const float4* kvg = reinterpret_cast<const float4*>(&g_kv[bh * DINc * DINc]);
    #pragma unroll
    for (int l = 0; l < 32; l++)
        reinterpret_cast<float4*>(sKV)[t + 128 * l] = kvg[t + 128 * l];
    #pragma unroll
    for (int l = 0; l < 16; l++) {
        int id = t + 128 * l;        // 0..2047 float4 slots
        int nl = id >> 5, d4 = id & 31;
        int fidx = ((b * NPGc + nbase + nl) * HHc + h) * DINc + d4 * 4;
        reinterpret_cast<float4*>(sQ)[id] = *reinterpret_cast<const float4*>(&g_q[fidx]);
    }
    __syncthreads();

    int m0 = (t >> 4) * 8;           // node group (0..56)
    int e0 = (t & 15) * 8;           // out-dim group

    float acc[8][8];
    float vs[8];
    *reinterpret_cast<float4*>(vs)     = *reinterpret_cast<float4*>(&g_vsum[bh * DINc + e0]);
    *reinterpret_cast<float4*>(vs + 4) = *reinterpret_cast<float4*>(&g_vsum[bh * DINc + e0 + 4]);
    #pragma unroll
    for (int i = 0; i < 8; i++)
        #pragma unroll
        for (int j = 0; j < 8; j++) acc[i][j] = vs[j];

    #pragma unroll 8
    for (int d = 0; d < 128; d++) {
        float qv[8], kvv[8];
        #pragma unroll
        for (int i = 0; i < 8; i++) qv[i] = sQ[(m0 + i) * 128 + d];
        *reinterpret_cast<float4*>(kvv)     = *reinterpret_cast<float4*>(&sKV[d * 128 + e0]);
        *reinterpret_cast<float4*>(kvv + 4) = *reinterpret_cast<float4*>(&sKV[d * 128 + e0 + 4]);
        #pragma unroll
        for (int i = 0; i < 8; i++)
            #pragma unroll
            for (int j = 0; j < 8; j++) acc[i][j] += qv[i] * kvv[j];
    }

    #pragma unroll
    for (int i = 0; i < 8; i++) {
        int gn = b * NPGc + nbase + m0 + i;
        float inv = 1.0f / g_den[gn * HHc + h];
        int base = (gn * HHc + h) * DINc + e0;
        #pragma unroll
        for (int j = 0; j < 8; j += 4) {
            float4 gc = *reinterpret_cast<float4*>(&g_gcn[base + j]);
            float4 av = *reinterpret_cast<float4*>(&g_acc[base + j]);
            float4 o;
            o.x = 0.5f * (gc.x + acc[i][j + 0] * inv);
            o.y = 0.5f * (gc.y + acc[i][j + 1] * inv);
            o.z = 0.5f * (gc.z + acc[i][j + 2] * inv);
            o.w = 0.5f * (gc.w + acc[i][j + 3] * inv);
            *reinterpret_cast<float4*>(&g_cur[base + j]) = o;
            av.x += o.x; av.y += o.y; av.z += o.z; av.w += o.w;
            *reinterpret_cast<float4*>(&g_acc[base + j]) = av;
        }
    }
}

// ---------------- launcher ----------------
extern "C" void kernel_launch(void* const* d_in, const int* in_sizes, int n_in,
                              void* d_out, int out_size) {
    const float* x    = (const float*)d_in[0];
    const float* Wq_w = (const float*)d_in[1];
    const float* Wq_b = (const float*)d_in[2];
    const float* Wk_w = (const float*)d_in[3];
    const float* Wk_b = (const float*)d_in[4];
    const float* Wo_w = (const float*)d_in[5];
    const float* Wo_b = (const float*)d_in[6];
    const int*   edge = (const int*)d_in[7];
    const int*   nnod = (const int*)d_in[8];
    const int* row = edge;
    const int* col = edge + EEc;
    float* out = (float*)d_out;

    float *pq, *pk, *pacc;
    cudaGetSymbolAddress((void**)&pq,   g_q);
    cudaGetSymbolAddress((void**)&pk,   g_k);
    cudaGetSymbolAddress((void**)&pacc, g_acc);
    cudaFuncSetAttribute(k_combine, cudaFuncAttributeMaxDynamicSharedMemorySize, 98304);

    // init + graph preprocessing (once per call)
    k_init<<<16384, 256>>>(x);
    k_zero_pre<<<128, 256>>>();
    k_count<<<1024, 256>>>(row);
    k_dis<<<128, 256>>>();
    k_scanA<<<128, 256>>>();
    k_scanB<<<1, 128>>>();
    k_scanC<<<128, 256>>>();
    k_fill<<<1024, 256>>>(row, col);

    // projections + normalization + invariant attention terms
    k_gemm<<<dim3(4, 256), 256>>>(x, Wq_w, Wq_b, pq, NN, CDIM, DINc, 1.0f);
    k_gemm<<<dim3(4, 256), 256>>>(x, Wk_w, Wk_b, pk, NN, CDIM, DINc, 1.0f);
    k_norm<<<16384, 256>>>(pq);
    k_norm<<<16384, 256>>>(pk);
    k_colsum<<<dim3(32, 32), 128>>>(0);     // ksum
    k_den<<<16384, 256>>>(nnod);

    // K_ORDER = 4 propagation steps
    for (int it = 0; it < 4; it++) {
        k_zero_iter<<<2048, 256>>>();
        k_colsum<<<dim3(32, 32), 128>>>(1); // vsum from cur
        k_kv<<<dim3(32, 8), 256>>>();
        k_gcn<<<32768, 128>>>();
        k_combine<<<dim3(32, 64), 128, 98304>>>();
    }

    // out = (acc @ Wo^T + b) / H
    k_gemm<<<dim3(1, 256), 256>>>(pacc, Wo_w, Wo_b, out, NN, DINc, CDIM, 0.25f);
}